// round 7
// baseline (speedup 1.0000x reference)
#include <cuda_runtime.h>

#define BB   8
#define CC   64
#define HH   128
#define WW   128
#define COUT 64
#define K2   9
#define HWSZ (HH*WW)        /* 16384 */
#define NPIX (BB*HWSZ)      /* 131072 */
#define PT   64             /* pixel tile per block */
#define PITCH 130           /* 2*PT + 2 pad */
#define CBUF (32*PITCH)     /* 4160 floats per col buffer */
#define WBUF 4096           /* floats per weight buffer (32 rows x 128) */
#define WOFF (2*CBUF)       /* 8320 */
#define SMEM_FLOATS (2*CBUF + 2*WBUF)          /* 16512 */
#define MBAR_BYTE_OFF (SMEM_FLOATS * 4)        /* 66048 */
#define SMEM_BYTES (MBAR_BYTE_OFF + 32)        /* 4 mbarriers */

typedef unsigned long long u64;

// scratch (allocation-free rule: __device__ globals)
__device__ __align__(16) float g_xt[(size_t)NPIX * CC];   // x in NHWC, 33.5 MB
__device__ __align__(16) float g_wt[K2 * 32 * COUT * 2];  // weights packed: [k*32+pair][o][2]

__device__ __forceinline__ u64 fma2(u64 a, u64 b, u64 c) {
    u64 d;
    asm("fma.rn.f32x2 %0, %1, %2, %3;" : "=l"(d) : "l"(a), "l"(b), "l"(c));
    return d;
}
__device__ __forceinline__ float lo32(u64 v) { return __uint_as_float((unsigned)v); }
__device__ __forceinline__ float hi32(u64 v) { return __uint_as_float((unsigned)(v >> 32)); }

__device__ __forceinline__ void cp16(void* s, const void* g) {
    unsigned a = (unsigned)__cvta_generic_to_shared(s);
    asm volatile("cp.async.cg.shared.global [%0], [%1], 16;\n" :: "r"(a), "l"(g) : "memory");
}
#define CP_COMMIT() asm volatile("cp.async.commit_group;\n" ::: "memory")
#define CP_WAIT0()  asm volatile("cp.async.wait_group 0;\n" ::: "memory")

// ---- mbarrier primitives (parity protocol; vendored from ptx_helpers) ----
__device__ __forceinline__ unsigned smem_u32(const void* p) {
    unsigned a;
    asm("{ .reg .u64 t; cvta.to.shared.u64 t, %1; cvt.u32.u64 %0, t; }" : "=r"(a) : "l"(p));
    return a;
}
#define MBARRIER_INIT(mbar, count) \
    asm volatile("mbarrier.init.shared.b64 [%0], %1;" :: "r"(mbar), "r"((unsigned)(count)) : "memory")
#define MBARRIER_ARRIVE(mbar) \
    asm volatile("mbarrier.arrive.shared.b64 _, [%0];" :: "r"(mbar) : "memory")
#define MBARRIER_WAIT_PARITY(mbar, parity) do {                                      \
    unsigned _m = (mbar), _p = (unsigned)(parity), _done;                            \
    asm volatile("{\n\t.reg .pred p;\n\t"                                            \
        "mbarrier.try_wait.parity.acquire.cta.shared::cta.b64 p, [%1], %2;\n\t"      \
        "selp.b32 %0, 1, 0, p;\n\t}"                                                 \
        : "=r"(_done) : "r"(_m), "r"(_p) : "memory");                                \
    if (!_done) {                                                                    \
        asm volatile("{\n\t.reg .pred P1;\n\t"                                       \
            "WL_%=:\n\t"                                                             \
            "mbarrier.try_wait.parity.acquire.cta.shared::cta.b64 P1, [%0], %1, 0x989680;\n\t" \
            "@P1 bra.uni WD_%=;\n\t"                                                 \
            "bra.uni WL_%=;\n\t"                                                     \
            "WD_%=:\n\t}" :: "r"(_m), "r"(_p) : "memory");                           \
    }                                                                                \
} while (0)

// ---------------- kernel 1: fused prep (transpose x + pack weights) ----------------
__global__ __launch_bounds__(256) void k_prep(const float* __restrict__ x,
                                              const float* __restrict__ w) {
    if (blockIdx.x >= 4096) {
        int i = (blockIdx.x - 4096) * 256 + threadIdx.x;
        if (i < K2 * 32 * COUT * 2) {
            int j = i & 1;
            int o = (i >> 1) & 63;
            int r = i >> 7;
            int c = 2 * (r & 31) + j;
            int k = r >> 5;
            g_wt[i] = w[(o * 64 + c) * 9 + k];
        }
        return;
    }
    __shared__ float s[64][33];
    const int px0  = blockIdx.x * 32;
    const int b    = px0 >> 14;
    const int pix0 = px0 & 16383;
    const int t    = threadIdx.x;
    const int lane = t & 31;
    const int cg   = t >> 5;
    #pragma unroll
    for (int cc = cg; cc < 64; cc += 8)
        s[cc][lane] = x[((size_t)(b * 64 + cc)) * HWSZ + pix0 + lane];
    __syncthreads();
    #pragma unroll
    for (int i = t; i < 2048; i += 256) {
        int c = i & 63;
        int p = i >> 6;
        g_xt[((size_t)(px0 + p)) * CC + c] = s[c][p];
    }
}

// ---------------- producer helpers ----------------
__device__ __forceinline__ void sampleTask(
    float dx, float dy, float m, float kyf, float kxf, int px_coord,
    const float* __restrict__ xb, float2 g[4], float a[4])
{
    const float py  = kyf + dy;
    const float px  = (float)(px_coord - 1) + kxf + dx;
    const float y0f = floorf(py), x0f = floorf(px);
    const float wy1 = py - y0f,  wx1 = px - x0f;
    const float wy0 = 1.f - wy1, wx0 = 1.f - wx1;
    const int iy = (int)y0f, ix = (int)x0f;
    const bool vy0 = (unsigned)iy < (unsigned)HH, vy1 = (unsigned)(iy + 1) < (unsigned)HH;
    const bool vx0 = (unsigned)ix < (unsigned)WW, vx1 = (unsigned)(ix + 1) < (unsigned)WW;
    const float2 z = make_float2(0.f, 0.f);
    const float* bp = xb + ((long)iy * WW + ix) * CC;
    g[0] = (vy0 && vx0) ? *(const float2*)(bp)               : z;
    g[1] = (vy0 && vx1) ? *(const float2*)(bp + CC)          : z;
    g[2] = (vy1 && vx0) ? *(const float2*)(bp + WW * CC)     : z;
    g[3] = (vy1 && vx1) ? *(const float2*)(bp + WW * CC + CC): z;
    a[0] = m * wy0 * wx0;
    a[1] = m * wy0 * wx1;
    a[2] = m * wy1 * wx0;
    a[3] = m * wy1 * wx1;
}

__device__ __forceinline__ void storeTask(
    float* __restrict__ colb, int lane, int plocal, const float2 g[4], const float a[4])
{
    float2 v;
    v.x = a[0] * g[0].x + a[1] * g[1].x + a[2] * g[2].x + a[3] * g[3].x;
    v.y = a[0] * g[0].y + a[1] * g[1].y + a[2] * g[2].y + a[3] * g[3].y;
    *(float2*)(colb + lane * PITCH + 2 * plocal) = v;
}

// sample one tap (16 tasks) with register-rotated A/B lookahead (no copies)
__device__ __forceinline__ void sampleTap(
    int kn, int h, int pbase, const float* __restrict__ offb,
    const float* __restrict__ mb, const float* __restrict__ xb,
    float* __restrict__ coln, int lane, int s)
{
    const int   kny = kn / 3;
    const float kyf = (float)(h - 1 + kny);
    const float kxf = (float)(kn - 3 * kny);
    const float* offx = offb + (size_t)(2 * kn) * HWSZ;
    const float* offy = offx + HWSZ;
    const float* mk   = mb + (size_t)kn * HWSZ;
    const int p0 = s * 16;

    float2 gA[4][4], gB[4][4];
    float  aA[4][4], aB[4][4];

    #define SGRP(grp, G, A)                                                          \
        _Pragma("unroll")                                                            \
        for (int j = 0; j < 4; j++) {                                                \
            const int tt = (grp) * 4 + j;                                            \
            sampleTask(offx[tt], offy[tt], mk[tt], kyf, kxf, pbase + tt, xb, G[j], A[j]); \
        }
    #define STGR(grp, G, A)                                                          \
        _Pragma("unroll")                                                            \
        for (int j = 0; j < 4; j++)                                                  \
            storeTask(coln, lane, p0 + (grp) * 4 + j, G[j], A[j]);

    SGRP(0, gA, aA);
    SGRP(1, gB, aB);
    STGR(0, gA, aA);
    SGRP(2, gA, aA);
    STGR(1, gB, aB);
    SGRP(3, gB, aB);
    STGR(2, gA, aA);
    STGR(3, gB, aB);
    #undef SGRP
    #undef STGR
}

// ---------------- kernel 2: warp-specialized, mbarrier-decoupled ----------------
__global__ __launch_bounds__(256, 2) void k_dcn_main(
    const float* __restrict__ offset, const float* __restrict__ mask,
    const float* __restrict__ bias, float* __restrict__ out)
{
    extern __shared__ float smem[];   // [col0|col1|w0|w1|mbarriers]
    const int t    = threadIdx.x;
    const int lane = t & 31;
    const int warp = t >> 5;          // 0..3 consumers, 4..7 producers
    const int blk  = blockIdx.x;
    const int w0   = (blk & 1) * PT;
    const int h    = (blk >> 1) & 127;
    const int b    = blk >> 8;

    const unsigned mb_base = smem_u32(smem) + MBAR_BYTE_OFF;
    const unsigned mb_full0  = mb_base;
    const unsigned mb_full1  = mb_base + 8;
    const unsigned mb_empty0 = mb_base + 16;
    const unsigned mb_empty1 = mb_base + 24;

    if (t == 0) {
        MBARRIER_INIT(mb_full0, 128);   // 128 producer threads arrive
        MBARRIER_INIT(mb_full1, 128);
        MBARRIER_INIT(mb_empty0, 128);  // 128 consumer threads arrive
        MBARRIER_INIT(mb_empty1, 128);
    }
    __syncthreads();

    if (warp >= 4) {
        // ================= PRODUCER =================
        const int s  = warp - 4;
        const int ts = t - 128;
        const int pbase = w0 + s * 16;
        const float* offb = offset + ((size_t)b * 18 * HH + h) * WW + pbase;
        const float* mb   = mask   + ((size_t)b *  9 * HH + h) * WW + pbase;
        const float* xb   = g_xt + (size_t)b * HWSZ * CC + lane * 2;

        #pragma unroll 1
        for (int kn = 0; kn < K2; kn++) {
            const int st = kn & 1;
            const unsigned mbE = st ? mb_empty1 : mb_empty0;
            const unsigned mbF = st ? mb_full1  : mb_full0;
            const int ph = ((kn >> 1) & 1) ^ 1;   // producer phase: first two waits pass
            MBARRIER_WAIT_PARITY(mbE, ph);
            // stage weights for tap kn
            float4* wd = (float4*)(smem + WOFF + st * WBUF);
            const float4* ws = (const float4*)(g_wt + (size_t)kn * WBUF);
            #pragma unroll
            for (int i = 0; i < 8; i++)
                cp16(wd + ts + i * 128, ws + ts + i * 128);
            CP_COMMIT();
            // sample tap kn into col buffer st
            sampleTap(kn, h, pbase, offb, mb, xb, smem + st * CBUF, lane, s);
            CP_WAIT0();
            MBARRIER_ARRIVE(mbF);
        }
    } else {
        // ================= CONSUMER =================
        const int pg = lane & 15;
        const int o0 = (warp * 2 + (lane >> 4)) * 8;
        u64 acc[4][8];
        #pragma unroll
        for (int i = 0; i < 4; i++)
            #pragma unroll
            for (int j = 0; j < 8; j++) acc[i][j] = 0ull;

        #pragma unroll 1
        for (int k = 0; k < K2; k++) {
            const int st = k & 1;
            const unsigned mbF = st ? mb_full1  : mb_full0;
            const unsigned mbE = st ? mb_empty1 : mb_empty0;
            const int ph = (k >> 1) & 1;
            MBARRIER_WAIT_PARITY(mbF, ph);
            const float* colc = smem + st * CBUF + 2 * pg;
            const u64*   wb   = (const u64*)(smem + WOFF + st * WBUF) + o0;
            #pragma unroll 4
            for (int r = 0; r < 32; r++) {
                const float* cs = colc + r * PITCH;
                u64 cc0 = *(const u64*)(cs);
                u64 cc1 = *(const u64*)(cs + 32);
                u64 cc2 = *(const u64*)(cs + 64);
                u64 cc3 = *(const u64*)(cs + 96);
                const ulonglong2* wp = (const ulonglong2*)(wb + (size_t)r * 64);
                ulonglong2 w01 = wp[0];
                ulonglong2 w23 = wp[1];
                ulonglong2 w45 = wp[2];
                ulonglong2 w67 = wp[3];
                acc[0][0] = fma2(cc0, w01.x, acc[0][0]);
                acc[1][0] = fma2(cc1, w01.x, acc[1][0]);
                acc[2][0] = fma2(cc2, w01.x, acc[2][0]);
                acc[3][0] = fma2(cc3, w01.x, acc[3][0]);
                acc[0][1] = fma2(cc0, w01.y, acc[0][1]);
                acc[1][1] = fma2(cc1, w01.y, acc[1][1]);
                acc[2][1] = fma2(cc2, w01.y, acc[2][1]);
                acc[3][1] = fma2(cc3, w01.y, acc[3][1]);
                acc[0][2] = fma2(cc0, w23.x, acc[0][2]);
                acc[1][2] = fma2(cc1, w23.x, acc[1][2]);
                acc[2][2] = fma2(cc2, w23.x, acc[2][2]);
                acc[3][2] = fma2(cc3, w23.x, acc[3][2]);
                acc[0][3] = fma2(cc0, w23.y, acc[0][3]);
                acc[1][3] = fma2(cc1, w23.y, acc[1][3]);
                acc[2][3] = fma2(cc2, w23.y, acc[2][3]);
                acc[3][3] = fma2(cc3, w23.y, acc[3][3]);
                acc[0][4] = fma2(cc0, w45.x, acc[0][4]);
                acc[1][4] = fma2(cc1, w45.x, acc[1][4]);
                acc[2][4] = fma2(cc2, w45.x, acc[2][4]);
                acc[3][4] = fma2(cc3, w45.x, acc[3][4]);
                acc[0][5] = fma2(cc0, w45.y, acc[0][5]);
                acc[1][5] = fma2(cc1, w45.y, acc[1][5]);
                acc[2][5] = fma2(cc2, w45.y, acc[2][5]);
                acc[3][5] = fma2(cc3, w45.y, acc[3][5]);
                acc[0][6] = fma2(cc0, w67.x, acc[0][6]);
                acc[1][6] = fma2(cc1, w67.x, acc[1][6]);
                acc[2][6] = fma2(cc2, w67.x, acc[2][6]);
                acc[3][6] = fma2(cc3, w67.x, acc[3][6]);
                acc[0][7] = fma2(cc0, w67.y, acc[0][7]);
                acc[1][7] = fma2(cc1, w67.y, acc[1][7]);
                acc[2][7] = fma2(cc2, w67.y, acc[2][7]);
                acc[3][7] = fma2(cc3, w67.y, acc[3][7]);
            }
            MBARRIER_ARRIVE(mbE);
        }

        // epilogue
        #pragma unroll
        for (int oi = 0; oi < 8; oi++) {
            const int o = o0 + oi;
            const float bo = __ldg(bias + o);
            float* op = out + (((size_t)b * COUT + o) * HH + h) * WW + w0 + pg;
            #pragma unroll
            for (int i = 0; i < 4; i++)
                op[16 * i] = lo32(acc[i][oi]) + hi32(acc[i][oi]) + bo;
        }
    }
}

extern "C" void kernel_launch(void* const* d_in, const int* in_sizes, int n_in,
                              void* d_out, int out_size) {
    const float* x      = (const float*)d_in[0];
    const float* offset = (const float*)d_in[1];
    const float* mask   = (const float*)d_in[2];
    const float* weight = (const float*)d_in[3];
    const float* bias   = (const float*)d_in[4];
    float* out = (float*)d_out;

    cudaFuncSetAttribute(k_dcn_main, cudaFuncAttributeMaxDynamicSharedMemorySize, SMEM_BYTES);

    k_prep<<<4096 + (K2 * 32 * COUT * 2 + 255) / 256, 256>>>(x, weight);
    k_dcn_main<<<BB * HH * (WW / PT), 256, SMEM_BYTES>>>(offset, mask, bias, out);
}

// round 14
// speedup vs baseline: 1.3328x; 1.3328x over previous
#include <cuda_runtime.h>
#include <cuda_bf16.h>

#define BB   8
#define CC   64
#define HH   128
#define WW   128
#define COUT 64
#define K2   9
#define HWSZ (HH*WW)        /* 16384 */
#define NPIX (BB*HWSZ)      /* 131072 */
#define PT   64             /* pixels per CTA (half row) */
#define APITCH 144          /* bytes per px row in A tiles: 64 bf16 + 16B pad */

#define SM_B(st)    ((st) * 16384)
#define SM_A(st, s) (32768 + (st) * 18432 + (s) * 9216)
#define SMEM_TOTAL  69632

typedef unsigned long long u64;

__device__ __align__(16) float g_xt[(size_t)NPIX * CC];     // x NHWC f32, 33.5 MB
__device__ __align__(16) unsigned g_wfrag[K2 * 4096];       // weights in B-fragment order

__device__ __forceinline__ unsigned smem_u32p(const void* p) {
    return (unsigned)__cvta_generic_to_shared(p);
}
__device__ __forceinline__ void cp16(void* s, const void* g) {
    asm volatile("cp.async.cg.shared.global [%0], [%1], 16;\n"
                 :: "r"(smem_u32p(s)), "l"(g) : "memory");
}
#define CP_COMMIT() asm volatile("cp.async.commit_group;\n" ::: "memory")
#define CP_WAIT0()  asm volatile("cp.async.wait_group 0;\n" ::: "memory")

__device__ __forceinline__ void ldmat4(unsigned r[4], unsigned addr) {
    asm volatile("ldmatrix.sync.aligned.m8n8.x4.shared.b16 {%0,%1,%2,%3}, [%4];"
                 : "=r"(r[0]), "=r"(r[1]), "=r"(r[2]), "=r"(r[3]) : "r"(addr));
}
__device__ __forceinline__ void mma_bf16(float d[4], const unsigned a[4],
                                         unsigned b0, unsigned b1) {
    asm volatile("mma.sync.aligned.m16n8k16.row.col.f32.bf16.bf16.f32 "
                 "{%0,%1,%2,%3}, {%4,%5,%6,%7}, {%8,%9}, {%0,%1,%2,%3};"
                 : "+f"(d[0]), "+f"(d[1]), "+f"(d[2]), "+f"(d[3])
                 : "r"(a[0]), "r"(a[1]), "r"(a[2]), "r"(a[3]), "r"(b0), "r"(b1));
}

// ---------------- kernel 1: prep ----------------
__global__ __launch_bounds__(256) void k_prep(const float* __restrict__ x,
                                              const float* __restrict__ w) {
    if (blockIdx.x >= 4096) {
        int i = (blockIdx.x - 4096) * 256 + threadIdx.x;
        if (i < K2 * 4096) {
            const int word = i & 1;
            const int lane = (i >> 1) & 31;
            const int kc   = (i >> 6) & 3;
            const int nb   = (i >> 8) & 7;
            const int s    = (i >> 11) & 1;
            const int k    = i >> 12;
            const int c0 = kc * 16 + 2 * (lane & 3) + (word ? 8 : 0);
            const int o  = nb * 8 + (lane >> 2);
            float v0 = w[(o * 64 + c0) * 9 + k];
            float v1 = w[(o * 64 + c0 + 1) * 9 + k];
            __nv_bfloat16 h0 = __float2bfloat16(v0);
            __nv_bfloat16 h1 = __float2bfloat16(v1);
            __nv_bfloat16 e0 = s ? __float2bfloat16(v0 - __bfloat162float(h0)) : h0;
            __nv_bfloat16 e1 = s ? __float2bfloat16(v1 - __bfloat162float(h1)) : h1;
            unsigned lo16 = (unsigned)__bfloat16_as_ushort(e0);
            unsigned hi16 = (unsigned)__bfloat16_as_ushort(e1);
            g_wfrag[((((k * 2 + s) * 8 + nb) * 4 + kc) * 32 + lane) * 2 + word] =
                lo16 | (hi16 << 16);
        }
        return;
    }
    __shared__ float sT[64][33];
    const int px0  = blockIdx.x * 32;
    const int b    = px0 >> 14;
    const int pix0 = px0 & 16383;
    const int t    = threadIdx.x;
    const int lane = t & 31;
    const int cg   = t >> 5;
    #pragma unroll
    for (int cc = cg; cc < 64; cc += 8)
        sT[cc][lane] = x[((size_t)(b * 64 + cc)) * HWSZ + pix0 + lane];
    __syncthreads();
    #pragma unroll
    for (int i = t; i < 2048; i += 256) {
        int c = i & 63;
        int p = i >> 6;
        g_xt[((size_t)(px0 + p)) * CC + c] = sT[c][p];
    }
}

// ---------------- sampling ----------------
__device__ __forceinline__ void sampleTask(
    float dx, float dy, float m, float kyf, float kxf, int px_coord,
    const float* __restrict__ xb, float2 g[4], float a[4])
{
    const float py  = kyf + dy;
    const float px  = (float)(px_coord - 1) + kxf + dx;
    const float y0f = floorf(py), x0f = floorf(px);
    const float wy1 = py - y0f,  wx1 = px - x0f;
    const float wy0 = 1.f - wy1, wx0 = 1.f - wx1;
    const int iy = (int)y0f, ix = (int)x0f;
    const bool vy0 = (unsigned)iy < (unsigned)HH, vy1 = (unsigned)(iy + 1) < (unsigned)HH;
    const bool vx0 = (unsigned)ix < (unsigned)WW, vx1 = (unsigned)(ix + 1) < (unsigned)WW;
    const float2 z = make_float2(0.f, 0.f);
    const float* bp = xb + ((long)iy * WW + ix) * CC;
    g[0] = (vy0 && vx0) ? *(const float2*)(bp)               : z;
    g[1] = (vy0 && vx1) ? *(const float2*)(bp + CC)          : z;
    g[2] = (vy1 && vx0) ? *(const float2*)(bp + WW * CC)     : z;
    g[3] = (vy1 && vx1) ? *(const float2*)(bp + WW * CC + CC): z;
    a[0] = m * wy0 * wx0;
    a[1] = m * wy0 * wx1;
    a[2] = m * wy1 * wx0;
    a[3] = m * wy1 * wx1;
}

__device__ __forceinline__ void cvtStore(
    char* __restrict__ smc, int Ahi, int Alo, int lane, int plocal,
    const float2 g[4], const float a[4])
{
    float vx = a[0] * g[0].x + a[1] * g[1].x + a[2] * g[2].x + a[3] * g[3].x;
    float vy = a[0] * g[0].y + a[1] * g[1].y + a[2] * g[2].y + a[3] * g[3].y;
    unsigned hi, lo;
    asm("cvt.rn.bf16x2.f32 %0, %1, %2;" : "=r"(hi) : "f"(vy), "f"(vx));
    float fh0 = __uint_as_float(hi << 16);
    float fh1 = __uint_as_float(hi & 0xffff0000u);
    asm("cvt.rn.bf16x2.f32 %0, %1, %2;" : "=r"(lo) : "f"(vy - fh1), "f"(vx - fh0));
    const int off = plocal * APITCH + lane * 4;
    *(unsigned*)(smc + Ahi + off) = hi;
    *(unsigned*)(smc + Alo + off) = lo;
}

__device__ __forceinline__ void sampleTap(
    int kn, int h, int w0, int warp, const float* __restrict__ offb,
    const float* __restrict__ mbp, const float* __restrict__ xb,
    char* __restrict__ smc, int Ahi, int Alo, int lane)
{
    const int   kny = kn / 3;
    const float kyf = (float)(h - 1 + kny);
    const float kxf = (float)(kn - 3 * kny);
    const float* offx = offb + (size_t)(2 * kn) * HWSZ;
    const float* offy = offx + HWSZ;
    const float* mk   = mbp + (size_t)kn * HWSZ;
    const int pl0 = warp * 8;
    const int pc0 = w0 + pl0;

    float2 gA[2][4], gB[2][4];
    float  aA[2][4], aB[2][4];

    #define SGRP(grp, G, A)                                                           \
        _Pragma("unroll")                                                             \
        for (int j = 0; j < 2; j++) {                                                 \
            const int tt = (grp) * 2 + j;                                             \
            sampleTask(offx[tt], offy[tt], mk[tt], kyf, kxf, pc0 + tt, xb, G[j], A[j]); \
        }
    #define STGR(grp, G, A)                                                           \
        _Pragma("unroll")                                                             \
        for (int j = 0; j < 2; j++)                                                   \
            cvtStore(smc, Ahi, Alo, lane, pl0 + (grp) * 2 + j, G[j], A[j]);

    SGRP(0, gA, aA);
    SGRP(1, gB, aB);
    STGR(0, gA, aA);
    SGRP(2, gA, aA);
    STGR(1, gB, aB);
    SGRP(3, gB, aB);
    STGR(2, gA, aA);
    STGR(3, gB, aB);
    #undef SGRP
    #undef STGR
}

// ---------------- kernel 2: HMMA main ----------------
__global__ __launch_bounds__(256, 2) void k_dcn_main(
    const float* __restrict__ offset, const float* __restrict__ mask,
    const float* __restrict__ bias, float* __restrict__ out)
{
    extern __shared__ char smc[];
    const int t    = threadIdx.x;
    const int lane = t & 31;
    const int warp = t >> 5;
    const int blk  = blockIdx.x;
    const int w0   = (blk & 1) * PT;
    const int h    = (blk >> 1) & 127;
    const int b    = blk >> 8;

    const float* xb   = g_xt + (size_t)b * HWSZ * CC + lane * 2;
    const float* offb = offset + ((size_t)b * 18 * HH + h) * WW + w0 + warp * 8;
    const float* mbp  = mask   + ((size_t)b *  9 * HH + h) * WW + w0 + warp * 8;

    const int m0   = (warp & 3) * 16;
    const int nbg0 = (warp >> 2) * 4;
    const int g    = lane >> 2;
    const int tig  = lane & 3;

    float acc[4][4];
    #pragma unroll
    for (int i = 0; i < 4; i++)
        #pragma unroll
        for (int j = 0; j < 4; j++) acc[i][j] = 0.f;

    {   // prologue: stage tap 0
        char* dst = smc + SM_B(0) + t * 64;
        const char* src = (const char*)g_wfrag + t * 64;
        cp16(dst,      src);
        cp16(dst + 16, src + 16);
        cp16(dst + 32, src + 32);
        cp16(dst + 48, src + 48);
        CP_COMMIT();
        sampleTap(0, h, w0, warp, offb, mbp, xb, smc, SM_A(0, 0), SM_A(0, 1), lane);
        CP_WAIT0();
    }
    __syncthreads();

    #pragma unroll 1
    for (int k = 0; k < K2; k++) {
        const int cur = k & 1, nxt = cur ^ 1;
        if (k < K2 - 1) {
            char* dst = smc + SM_B(nxt) + t * 64;
            const char* src = (const char*)g_wfrag + (size_t)(k + 1) * 16384 + t * 64;
            cp16(dst,      src);
            cp16(dst + 16, src + 16);
            cp16(dst + 32, src + 32);
            cp16(dst + 48, src + 48);
            CP_COMMIT();
            sampleTap(k + 1, h, w0, warp, offb, mbp, xb,
                      smc, SM_A(nxt, 0), SM_A(nxt, 1), lane);
        }
        const unsigned Ah = smem_u32p(smc + SM_A(cur, 0));
        const unsigned Al = smem_u32p(smc + SM_A(cur, 1));
        const int mtx = lane >> 3;
        const unsigned arow = (unsigned)((m0 + ((mtx & 1) * 8) + (lane & 7)) * APITCH
                                         + (mtx >> 1) * 16);
        const char* Bc = smc + SM_B(cur);
        #pragma unroll
        for (int kc = 0; kc < 4; kc++) {
            unsigned ah[4], al[4];
            ldmat4(ah, Ah + arow + kc * 32);
            ldmat4(al, Al + arow + kc * 32);
            #pragma unroll
            for (int nbl = 0; nbl < 4; nbl++) {
                const int nb = nbg0 + nbl;
                const uint2 bh = *(const uint2*)(Bc + (nb * 4 + kc) * 256 + lane * 8);
                const uint2 bl = *(const uint2*)(Bc + ((8 + nb) * 4 + kc) * 256 + lane * 8);
                mma_bf16(acc[nbl], ah, bh.x, bh.y);
                mma_bf16(acc[nbl], ah, bl.x, bl.y);
                mma_bf16(acc[nbl], al, bh.x, bh.y);
            }
        }
        if (k < K2 - 1) CP_WAIT0();
        __syncthreads();
    }

    const int pxg = w0 + m0 + g;
    #pragma unroll
    for (int nbl = 0; nbl < 4; nbl++) {
        const int o0 = (nbg0 + nbl) * 8 + 2 * tig;
        const float b0v = __ldg(bias + o0);
        const float b1v = __ldg(bias + o0 + 1);
        float* op0 = out + (((size_t)b * COUT + o0) * HH + h) * WW + pxg;
        float* op1 = out + (((size_t)b * COUT + o0 + 1) * HH + h) * WW + pxg;
        op0[0] = acc[nbl][0] + b0v;
        op1[0] = acc[nbl][1] + b1v;
        op0[8] = acc[nbl][2] + b0v;
        op1[8] = acc[nbl][3] + b1v;
    }
}

extern "C" void kernel_launch(void* const* d_in, const int* in_sizes, int n_in,
                              void* d_out, int out_size) {
    const float* x      = (const float*)d_in[0];
    const float* offset = (const float*)d_in[1];
    const float* mask   = (const float*)d_in[2];
    const float* weight = (const float*)d_in[3];
    const float* bias   = (const float*)d_in[4];
    float* out = (float*)d_out;

    cudaFuncSetAttribute(k_dcn_main, cudaFuncAttributeMaxDynamicSharedMemorySize, SMEM_TOTAL);

    k_prep<<<4096 + (K2 * 4096 + 255) / 256, 256>>>(x, weight);
    k_dcn_main<<<BB * HH * 2, 256, SMEM_TOTAL>>>(offset, mask, bias, out);
}